// round 14
// baseline (speedup 1.0000x reference)
#include <cuda_runtime.h>
#include <cstddef>

#define B_   32
#define T_   2048
#define E_   128
#define G_   4              // CTAs per batch
#define ROWS 512            // T_ / G_  rows per CTA
#define NW   16             // warps per CTA
#define RPW  32             // rows per warp
#define THREADS 512
#define INV_T (1.0f / 2048.0f)

// ---------------- scratch (device globals; zero-init; no allocation) -------
__device__ float  g_s_part[2][B_][G_][E_];
__device__ float  g_c_part[2][B_][G_][E_];
__device__ float2 g_stats [2][B_][G_];
__device__ float  g_o_part[2][B_][G_][E_];
__device__ unsigned g_bar[B_][5];          // per-batch phase counters (self-reset)

static __device__ __forceinline__ float dot4(float4 a, float4 b) {
    return fmaf(a.x, b.x, fmaf(a.y, b.y, fmaf(a.z, b.z, a.w * b.w)));
}
static __device__ __forceinline__ float wsum(float v) {
    #pragma unroll
    for (int off = 16; off; off >>= 1) v += __shfl_xor_sync(0xffffffffu, v, off);
    return v;
}
static __device__ __forceinline__ float wmax(float v) {
    #pragma unroll
    for (int off = 16; off; off >>= 1) v = fmaxf(v, __shfl_xor_sync(0xffffffffu, v, off));
    return v;
}

// batch-scoped barrier: all G_ CTAs of this batch arrive, then proceed.
// 128 CTAs (512 thr, ~21KB smem) are trivially co-resident on 148 SMs.
static __device__ __forceinline__ void batch_bar(unsigned* cnt) {
    __threadfence();
    __syncthreads();
    if (threadIdx.x == 0) {
        atomicAdd(cnt, 1u);
        while (*(volatile unsigned*)cnt < G_) __nanosleep(32);
        __threadfence();
    }
    __syncthreads();
}

// ===========================================================================
__global__ void __launch_bounds__(THREADS, 1) fused_attn(
    const float* __restrict__ x1, const float* __restrict__ x2,
    const float* __restrict__ W1, const float* __restrict__ bb1,
    const float* __restrict__ U1, const float* __restrict__ W2,
    const float* __restrict__ bb2, const float* __restrict__ U2,
    float* __restrict__ out)
{
    const int b    = blockIdx.x >> 2;
    const int g    = blockIdx.x & 3;
    const int tid  = threadIdx.x;
    const int lane = tid & 31;
    const int w    = tid >> 5;
    const int t0   = g * ROWS;
    const int rbase = w * RPW;

    __shared__ float4 sred[2][NW][32];   // 16 KB warp-reduction scratch
    __shared__ float  vsh[2][E_];        // s (phase B) then c (phase C)
    __shared__ float  tsh[2][ROWS];      // d -> et -> softmax weights
    __shared__ float2 stsh[2][NW];       // per-warp softmax stats
    __shared__ float  s_m[2], s_iz[2];

    const float4* p1 = (const float4*)(x1 + ((size_t)b * T_ + t0) * E_);
    const float4* p2 = (const float4*)(x2 + ((size_t)b * T_ + t0) * E_);

    // ======== Phase A: streaming column sums, 8-row deep load batches ======
    {
        float4 s1a = {0,0,0,0}, s2a = {0,0,0,0};
        #pragma unroll
        for (int rb = 0; rb < RPW; rb += 8) {
            float4 v1[8], v2[8];
            #pragma unroll
            for (int k = 0; k < 8; k++) {
                v1[k] = __ldg(p1 + (rbase + rb + k) * 32 + lane);
                v2[k] = __ldg(p2 + (rbase + rb + k) * 32 + lane);
            }
            #pragma unroll
            for (int k = 0; k < 8; k++) {
                s1a.x += v1[k].x; s1a.y += v1[k].y; s1a.z += v1[k].z; s1a.w += v1[k].w;
                s2a.x += v2[k].x; s2a.y += v2[k].y; s2a.z += v2[k].z; s2a.w += v2[k].w;
            }
        }
        sred[0][w][lane] = s1a;
        sred[1][w][lane] = s2a;
        __syncthreads();
        if (tid < 64) {
            int ti = tid >> 5;
            float4 s = sred[ti][0][lane];
            #pragma unroll
            for (int k = 1; k < NW; k++) {
                float4 v = sred[ti][k][lane];
                s.x += v.x; s.y += v.y; s.z += v.z; s.w += v.w;
            }
            ((float4*)&g_s_part[ti][b][g][0])[lane] = s;
        }
    }
    batch_bar(&g_bar[b][0]);

    if (tid < 256) {
        int ti = tid >> 7, e = tid & 127;
        float acc = 0.f;
        #pragma unroll
        for (int gg = 0; gg < G_; gg++) acc += g_s_part[ti][b][gg][e];
        vsh[ti][e] = acc;
    }
    __syncthreads();

    // ======== Phase B: c partials + row dots d, 4-row batches ==============
    {
        float4 s1l = ((const float4*)vsh[0])[lane];
        float4 s2l = ((const float4*)vsh[1])[lane];
        float4 w1l = ((const float4*)W1)[lane];
        float4 w2l = ((const float4*)W2)[lane];
        float4 c1a = {0,0,0,0}, c2a = {0,0,0,0};
        #pragma unroll
        for (int rb = 0; rb < RPW; rb += 4) {
            float4 v1[4], v2[4];
            #pragma unroll
            for (int k = 0; k < 4; k++) {
                v1[k] = __ldg(p1 + (rbase + rb + k) * 32 + lane);
                v2[k] = __ldg(p2 + (rbase + rb + k) * 32 + lane);
            }
            float q[4][4];                  // [row][a1,a2,d1,d2] - 16 indep chains
            #pragma unroll
            for (int k = 0; k < 4; k++) {
                q[k][0] = dot4(v1[k], s2l);
                q[k][1] = dot4(v2[k], s1l);
                q[k][2] = dot4(v1[k], w1l);
                q[k][3] = dot4(v2[k], w2l);
            }
            #pragma unroll
            for (int k = 0; k < 4; k++) {
                #pragma unroll
                for (int i = 0; i < 4; i++) {
                    q[k][i] += __shfl_xor_sync(0xffffffffu, q[k][i], 16);
                    q[k][i] += __shfl_xor_sync(0xffffffffu, q[k][i], 8);
                }
            }
            float qq[4];
            #pragma unroll
            for (int k = 0; k < 4; k++)
                qq[k] = (lane < 8) ? q[k][0] : (lane < 16) ? q[k][1]
                      : (lane < 24) ? q[k][2] : q[k][3];
            #pragma unroll
            for (int k = 0; k < 4; k++) {
                qq[k] += __shfl_xor_sync(0xffffffffu, qq[k], 4);
                qq[k] += __shfl_xor_sync(0xffffffffu, qq[k], 2);
                qq[k] += __shfl_xor_sync(0xffffffffu, qq[k], 1);
            }
            #pragma unroll
            for (int k = 0; k < 4; k++) {
                int row = rbase + rb + k;
                float a1 = __shfl_sync(0xffffffffu, qq[k], 0);
                float a2 = __shfl_sync(0xffffffffu, qq[k], 8);
                if (lane == 16) tsh[0][row] = qq[k];   // d1
                if (lane == 24) tsh[1][row] = qq[k];   // d2
                c1a.x = fmaf(a1, v2[k].x, c1a.x); c1a.y = fmaf(a1, v2[k].y, c1a.y);
                c1a.z = fmaf(a1, v2[k].z, c1a.z); c1a.w = fmaf(a1, v2[k].w, c1a.w);
                c2a.x = fmaf(a2, v1[k].x, c2a.x); c2a.y = fmaf(a2, v1[k].y, c2a.y);
                c2a.z = fmaf(a2, v1[k].z, c2a.z); c2a.w = fmaf(a2, v1[k].w, c2a.w);
            }
        }
        sred[0][w][lane] = c1a;
        sred[1][w][lane] = c2a;
        __syncthreads();
        if (tid < 64) {
            int ti = tid >> 5;
            float4 s = sred[ti][0][lane];
            #pragma unroll
            for (int k = 1; k < NW; k++) {
                float4 v = sred[ti][k][lane];
                s.x += v.x; s.y += v.y; s.z += v.z; s.w += v.w;
            }
            ((float4*)&g_c_part[ti][b][g][0])[lane] = s;
        }
    }
    batch_bar(&g_bar[b][1]);

    if (tid < 256) {
        int ti = tid >> 7, e = tid & 127;
        float acc = 0.f;
        #pragma unroll
        for (int gg = 0; gg < G_; gg++) acc += g_c_part[ti][b][gg][e];
        vsh[ti][e] = acc * INV_T;
    }
    __syncthreads();

    // ======== Phase C: logits + per-CTA softmax stats (p-loop) =============
    {
        int tloc = w * 32 + lane;           // 0..511
        #pragma unroll
        for (int p = 0; p < 2; p++) {
            const float* U    = p ? U2  : U1;
            const float* bias = p ? bb2 : bb1;
            int t = t0 + tloc;
            float acc = 0.f;
            #pragma unroll 8
            for (int e = 0; e < E_; e++)
                acc = fmaf(vsh[p][e], __ldg(&U[e * T_ + t]), acc);
            float et = acc + tsh[p][tloc] + __ldg(&bias[t]);
            tsh[p][tloc] = et;              // same thread owns (p,tloc): safe
            float m = wmax(et);
            float z = wsum(__expf(et - m));
            if (lane == 0) stsh[p][w] = make_float2(m, z);
        }
    }
    __syncthreads();
    if (tid < 2) {
        float m = -3.4e38f;
        #pragma unroll
        for (int i = 0; i < NW; i++) m = fmaxf(m, stsh[tid][i].x);
        float z = 0.f;
        #pragma unroll
        for (int i = 0; i < NW; i++) {
            float2 st = stsh[tid][i];
            z += st.y * __expf(st.x - m);
        }
        g_stats[tid][b][g] = make_float2(m, z);
    }
    batch_bar(&g_bar[b][2]);
    if (tid < 2) {
        float m = -3.4e38f;
        #pragma unroll
        for (int gg = 0; gg < G_; gg++) m = fmaxf(m, g_stats[tid][b][gg].x);
        float z = 0.f;
        #pragma unroll
        for (int gg = 0; gg < G_; gg++) {
            float2 st = g_stats[tid][b][gg];
            z += st.y * __expf(st.x - m);
        }
        s_m[tid]  = m;
        s_iz[tid] = 1.0f / z;
    }
    __syncthreads();

    // ======== Phase D: softmax weights + weighted sums, 8-row batches ======
    {
        int tloc = w * 32 + lane;
        #pragma unroll
        for (int p = 0; p < 2; p++)
            tsh[p][tloc] = __expf(tsh[p][tloc] - s_m[p]) * s_iz[p];
    }
    __syncthreads();
    {
        float4 o1a = {0,0,0,0}, o2a = {0,0,0,0};
        #pragma unroll
        for (int rb = 0; rb < RPW; rb += 8) {
            float4 v1[8], v2[8];
            #pragma unroll
            for (int k = 0; k < 8; k++) {
                v1[k] = __ldg(p1 + (rbase + rb + k) * 32 + lane);
                v2[k] = __ldg(p2 + (rbase + rb + k) * 32 + lane);
            }
            #pragma unroll
            for (int k = 0; k < 8; k++) {
                int row = rbase + rb + k;
                float wt1 = tsh[0][row];
                float wt2 = tsh[1][row];
                o1a.x = fmaf(wt1, v1[k].x, o1a.x); o1a.y = fmaf(wt1, v1[k].y, o1a.y);
                o1a.z = fmaf(wt1, v1[k].z, o1a.z); o1a.w = fmaf(wt1, v1[k].w, o1a.w);
                o2a.x = fmaf(wt2, v2[k].x, o2a.x); o2a.y = fmaf(wt2, v2[k].y, o2a.y);
                o2a.z = fmaf(wt2, v2[k].z, o2a.z); o2a.w = fmaf(wt2, v2[k].w, o2a.w);
            }
        }
        sred[0][w][lane] = o1a;
        sred[1][w][lane] = o2a;
        __syncthreads();
        if (tid < 64) {
            int ti = tid >> 5;
            float4 s = sred[ti][0][lane];
            #pragma unroll
            for (int k = 1; k < NW; k++) {
                float4 v = sred[ti][k][lane];
                s.x += v.x; s.y += v.y; s.z += v.z; s.w += v.w;
            }
            ((float4*)&g_o_part[ti][b][g][0])[lane] = s;
        }
    }
    batch_bar(&g_bar[b][3]);

    // ---------------- output: CTA g writes its 64 of 256 values ------------
    if (tid < 64) {
        int idx = g * 64 + tid;
        int ti = idx >> 7, e = idx & 127;
        float acc = 0.f;
        #pragma unroll
        for (int gg = 0; gg < G_; gg++) acc += g_o_part[ti][b][gg][e];
        out[b * 256 + idx] = acc;
    }

    // ---------------- cleanup: last CTA of the batch resets counters -------
    __syncthreads();
    if (tid == 0) {
        unsigned old = atomicAdd(&g_bar[b][4], 1u);
        if (old == G_ - 1) {
            #pragma unroll
            for (int i = 0; i < 5; i++) g_bar[b][i] = 0u;
        }
    }
}

// ===========================================================================
extern "C" void kernel_launch(void* const* d_in, const int* in_sizes, int n_in,
                              void* d_out, int out_size)
{
    const float* x1 = (const float*)d_in[0];
    const float* x2 = (const float*)d_in[1];
    const float* W1 = (const float*)d_in[2];
    const float* b1 = (const float*)d_in[3];
    const float* U1 = (const float*)d_in[4];
    const float* W2 = (const float*)d_in[5];
    const float* b2 = (const float*)d_in[6];
    const float* U2 = (const float*)d_in[7];
    float* out = (float*)d_out;

    fused_attn<<<B_ * G_, THREADS>>>(x1, x2, W1, b1, U1, W2, b2, U2, out);
}